// round 14
// baseline (speedup 1.0000x reference)
#include <cuda_runtime.h>
#include <cuda_bf16.h>
#include <cuda_fp16.h>
#include <cstdint>

// Problem constants
#define NNODES 8192
#define DN  64
#define DE  64
#define IUU 128
#define BE  524288
#define BN  65536
#define TILE 128
#define NTILES (BE / TILE)     // 4096
#define THREADS 256            // 1 CTA per SM, high-register

// Device-global scratch (no allocation allowed)
__device__ float    g_sums[(size_t)BN * DN];   // 16 MB
__device__ float    g_cnts[BN];
// fp16 P table, thread-swizzled: per node 128 uint32 = [Pr 64 | Ps 64] packs.
__device__ uint32_t g_Ph[(size_t)BN * 128];    // 32 MB

// ---------------- edge-kernel smem layout (bytes) -- R12 layout ----------
#define SM_RS   0                        // 2 x 128 ints (double buffered)
#define SM_SS   1024                     // 2 x 128 ints
#define SM_BO   2048                     // 64 f
#define SM_BE2  2304                     // 64 f
#define SM_W1   4096                     // W_in edge part: 64 frags * 256 = 16384
#define SM_W2   20480                    // W_out staging: 16384
#define SM_W3   36864                    // W_edge staging: 8192
#define SM_AB   45056                    // h frags 32768 (fp16); e frags overlay first 16384
#define SM_PING 77824                    // 2 x 16384 edge-chunk fp16 frag buffers
#define SMEM_TOTAL 110592

// ---------------- pnode-kernel smem layout (64-row blocks) ----------------
#define PROWS   64
#define PSM_W   0                        // 128 frags * 256B = 32768
#define PSM_A   32768                    // 64x64 fp16 A-frags: 8192
#define PSM_B   40960                    // 128 f bias
#define PSM_TOTAL 41472
#define PTHREADS 256

// ---------------------------------------------------------------------------
__device__ __forceinline__ void mma_f16(float* c, const uint32_t* a,
                                        uint32_t b0, uint32_t b1) {
    asm volatile(
        "mma.sync.aligned.m16n8k16.row.col.f32.f16.f16.f32 "
        "{%0,%1,%2,%3},{%4,%5,%6,%7},{%8,%9},{%0,%1,%2,%3};"
        : "+f"(c[0]), "+f"(c[1]), "+f"(c[2]), "+f"(c[3])
        : "r"(a[0]), "r"(a[1]), "r"(a[2]), "r"(a[3]), "r"(b0), "r"(b1));
}

__device__ __forceinline__ uint32_t pack_h2(float x, float y) {
    __half2 h = __floats2half2_rn(x, y);
    return *reinterpret_cast<uint32_t*>(&h);
}
__device__ __forceinline__ float2 h2f2(uint32_t w) {
    return __half22float2(*reinterpret_cast<__half2*>(&w));
}

// Weights -> fp16 B-frags, hi only (uint2/lane, 256B/frag). W [K, NT*8] row-major.
__device__ __forceinline__ void load_wfrag_h(const float* __restrict__ W, int K, int NT,
                                             char* dst, int wid, int lane, int nwarps) {
    const int g = lane >> 2, t = lane & 3;
    const int Nw = NT * 8;
    const int SF = K / 16;
    for (int f = wid; f < SF * NT; f += nwarps) {
        int s = f / NT, j = f - s * NT;
        int n = j * 8 + g;
        uint2 v;
        #pragma unroll
        for (int r = 0; r < 2; r++) {
            int k = s * 16 + 2 * t + 8 * r;
            ((uint32_t*)&v)[r] = pack_h2(W[(size_t)k * Nw + n], W[(size_t)(k + 1) * Nw + n]);
        }
        *(uint2*)(dst + (size_t)f * 256 + lane * 8) = v;
    }
}

// ---------------------------------------------------------------------------
// Ph[n] = fp16([nodes[n]@W_in[0:64]+b_in  ||  nodes[n]@W_in[128:192]]), swizzled.
// 64 node rows per CTA (1024 blocks) for fine-grained latency interleave.
__global__ __launch_bounds__(PTHREADS, 2)
void pnode_kernel(const float* __restrict__ nodes,
                  const float* __restrict__ W_in,
                  const float* __restrict__ b_in)
{
    extern __shared__ char sm[];
    const int tid  = threadIdx.x;
    const int lane = tid & 31;
    const int wid  = tid >> 5;
    const int g = lane >> 2, t = lane & 3;
    const int wm = wid & 3;                // mtile 0..3 (16 rows each)
    const int wn = wid >> 2;               // N half (0/1)

    // Wbig [64, 256]: n<128 -> W_in[k][n] (receiver); else W_in[128+k][n-128]
    for (int f = wid; f < 4 * 32; f += (PTHREADS / 32)) {
        int s = f >> 5, j = f & 31;
        int n = j * 8 + g;
        uint2 v;
        #pragma unroll
        for (int r = 0; r < 2; r++) {
            int k = s * 16 + 2 * t + 8 * r;
            float x, y;
            if (n < 128) { x = W_in[(size_t)k * IUU + n];         y = W_in[(size_t)(k + 1) * IUU + n]; }
            else         { x = W_in[(size_t)(128 + k) * IUU + n - 128];
                           y = W_in[(size_t)(129 + k) * IUU + n - 128]; }
            ((uint32_t*)&v)[r] = pack_h2(x, y);
        }
        *(uint2*)(sm + PSM_W + (size_t)f * 256 + lane * 8) = v;
    }
    if (tid < IUU) ((float*)(sm + PSM_B))[tid] = b_in[tid];

    // gather A: 64 node rows x 64 cols -> fp16 frags (float4 loads)
    const int m0 = blockIdx.x * PROWS;
    const float4* nbase = (const float4*)(nodes + (size_t)m0 * DN);
    #pragma unroll
    for (int ii = 0; ii < 4; ii++) {
        int idx = tid + ii * PTHREADS;           // 1024 float4 units
        float4 v = nbase[idx];
        int e = idx >> 4, jf = idx & 15;
        int sl = jf >> 2;
        int rg = ((e >> 3) & 1) | (((jf >> 1) & 1) << 1);
        char* pbase = sm + PSM_A + (((e >> 4 << 2) + sl) << 9) + rg * 4;
        int j0 = 2 * jf;
        *(uint32_t*)(pbase + (((e & 7) << 2) | (j0 & 3)) * 16)       = pack_h2(v.x, v.y);
        *(uint32_t*)(pbase + (((e & 7) << 2) | ((j0 + 1) & 3)) * 16) = pack_h2(v.z, v.w);
    }
    __syncthreads();

    const float* bi = (const float*)(sm + PSM_B);
    #pragma unroll
    for (int np = 0; np < 2; np++) {
        float C[8][4];
        #pragma unroll
        for (int b = 0; b < 8; b++)
            #pragma unroll
            for (int c = 0; c < 4; c++) C[b][c] = 0.f;
        #pragma unroll
        for (int sl = 0; sl < 4; sl++) {
            uint4 A = *(const uint4*)(sm + PSM_A + (((wm << 2) + sl) << 9) + lane * 16);
            #pragma unroll
            for (int j8 = 0; j8 < 8; j8++) {
                int jg = wn * 16 + np * 8 + j8;
                uint2 B = *(const uint2*)(sm + PSM_W + (size_t)(sl * 32 + jg) * 256 + lane * 8);
                mma_f16(C[j8], (const uint32_t*)&A, B.x, B.y);
            }
        }
        // vectorized store: 8 consecutive packs per (row, np)
        {
            int row = m0 + wm * 16 + g;
            uint32_t pa[8], pb[8];
            #pragma unroll
            for (int j8 = 0; j8 < 8; j8++) {
                int col = (wn * 16 + np * 8 + j8) * 8 + t * 2;
                float bx = (wn == 0) ? bi[col]     : 0.f;
                float by = (wn == 0) ? bi[col + 1] : 0.f;
                pa[j8] = pack_h2(C[j8][0] + bx, C[j8][1] + by);
                pb[j8] = pack_h2(C[j8][2] + bx, C[j8][3] + by);
            }
            size_t base = (size_t)row * 128 + wn * 64 + t * 16 + np * 8;
            *(uint4*)&g_Ph[base]     = *(uint4*)&pa[0];
            *(uint4*)&g_Ph[base + 4] = *(uint4*)&pa[4];
            size_t base2 = base + (size_t)8 * 128;
            *(uint4*)&g_Ph[base2]     = *(uint4*)&pb[0];
            *(uint4*)&g_Ph[base2 + 4] = *(uint4*)&pb[4];
        }
    }
}

// ---------------------------------------------------------------------------
// 256 threads, 1 CTA/SM, persistent-register B (R12 structure, 4 barriers).
__global__ __launch_bounds__(THREADS, 1)
void edge_kernel(const float* __restrict__ edges,
                 const int*   __restrict__ senders,
                 const int*   __restrict__ receivers,
                 const float* __restrict__ W_in,
                 const float* __restrict__ W_out, const float* __restrict__ b_out,
                 const float* __restrict__ W_edge,const float* __restrict__ b_edge,
                 float* __restrict__ out_edges,
                 float* __restrict__ out_s, float* __restrict__ out_r)
{
    extern __shared__ char sm[];
    const int tid  = threadIdx.x;
    const int lane = tid & 31;
    const int wid  = tid >> 5;
    const int g = lane >> 2, t = lane & 3;
    const int wm = wid & 3;                 // M band: rows 32*wm (2 frags)
    const int wn = wid >> 2;                // N half (0/1)

    load_wfrag_h(W_in + 64 * IUU, 64, 16, sm + SM_W1, wid, lane, THREADS / 32);
    load_wfrag_h(W_out, 128, 8, sm + SM_W2, wid, lane, THREADS / 32);
    load_wfrag_h(W_edge, 64, 8, sm + SM_W3, wid, lane, THREADS / 32);
    if (tid < DN) ((float*)(sm + SM_BO))[tid]  = b_out[tid];
    if (tid < DE) ((float*)(sm + SM_BE2))[tid] = b_edge[tid];
    __syncthreads();

    // persistent-register B fragments for GEMM2 / GEMM3
    uint2 B2r[8][4];
    #pragma unroll
    for (int s2 = 0; s2 < 8; s2++)
        #pragma unroll
        for (int j4 = 0; j4 < 4; j4++)
            B2r[s2][j4] = *(const uint2*)(sm + SM_W2 +
                          (size_t)(s2 * 8 + (wn << 2) + j4) * 256 + lane * 8);
    uint2 B3r[4][4];
    #pragma unroll
    for (int s3 = 0; s3 < 4; s3++)
        #pragma unroll
        for (int j4 = 0; j4 < 4; j4++)
            B3r[s3][j4] = *(const uint2*)(sm + SM_W3 +
                          (size_t)(s3 * 8 + (wn << 2) + j4) * 256 + lane * 8);

    const float* bo = (const float*)(sm + SM_BO);
    const float* be = (const float*)(sm + SM_BE2);

    // prologue: tile0 indices + edge chunk (fp16) into buffer 0
    {
        int tile0 = blockIdx.x;
        if (tid < TILE) {
            int ge = tile0 * TILE + tid, b = ge >> 16;
            int rraw = receivers[ge], sraw = senders[ge];
            out_r[ge] = (float)rraw;
            out_s[ge] = (float)sraw;
            int nr = rraw + (b << 13);
            ((int*)(sm + SM_RS))[tid] = nr;
            ((int*)(sm + SM_SS))[tid] = sraw + (b << 13);
            atomicAdd(&g_cnts[nr], 1.0f);
        }
        const float4* ebase = (const float4*)(edges + (size_t)tile0 * TILE * DE);
        #pragma unroll
        for (int ii = 0; ii < 8; ii++) {
            int idx = tid + ii * THREADS;
            float4 v = ebase[idx];
            int e = idx >> 4, jf = idx & 15;
            int sl = jf >> 2;
            int rg = ((e >> 3) & 1) | (((jf >> 1) & 1) << 1);
            char* pbase = sm + SM_PING + (((e >> 4 << 2) + sl) << 9) + rg * 4;
            int j0 = 2 * jf;
            *(uint32_t*)(pbase + (((e & 7) << 2) | (j0 & 3)) * 16)       = pack_h2(v.x, v.y);
            *(uint32_t*)(pbase + (((e & 7) << 2) | ((j0 + 1) & 3)) * 16) = pack_h2(v.z, v.w);
        }
    }
    __syncthreads();

    int pb = 0;
    for (int tile = blockIdx.x; tile < NTILES; tile += gridDim.x, pb ^= 1) {
        const int e0 = tile * TILE;
        const int* rs  = (const int*)(sm + SM_RS) + pb * TILE;
        const int* ssn = (const int*)(sm + SM_SS) + pb * TILE;

        // ---- prefetch next tile ----
        const int nt = tile + (int)gridDim.x;
        const bool valid = nt < NTILES;
        float4 ev[8];
        int nr = 0, nss = 0;
        if (valid) {
            const float4* ebase = (const float4*)(edges + (size_t)nt * TILE * DE);
            #pragma unroll
            for (int ii = 0; ii < 8; ii++) ev[ii] = ebase[tid + ii * THREADS];
            if (tid < TILE) {
                int ge = nt * TILE + tid, b = ge >> 16;
                int rraw = receivers[ge], sraw = senders[ge];
                out_r[ge] = (float)rraw;
                out_s[ge] = (float)sraw;
                nr  = rraw + (b << 13);
                nss = sraw + (b << 13);
            }
        }

        // ============ GEMM1 (edge chunk, 1-term): [128,64] @ W1h ============
        float C1[2][8][4];
        #pragma unroll
        for (int a = 0; a < 2; a++)
            #pragma unroll
            for (int b = 0; b < 8; b++)
                #pragma unroll
                for (int c = 0; c < 4; c++) C1[a][b][c] = 0.f;
        {
            const char* abase = sm + SM_PING + pb * 16384;
            #pragma unroll
            for (int sl = 0; sl < 4; sl++) {
                uint4 A[2];
                #pragma unroll
                for (int m2 = 0; m2 < 2; m2++) {
                    int mt = (wm << 1) + m2;
                    A[m2] = *(const uint4*)(abase + (((mt << 2) + sl) << 9) + lane * 16);
                }
                #pragma unroll
                for (int j8 = 0; j8 < 8; j8++) {
                    int jg = (wn << 3) + j8;
                    uint2 B = *(const uint2*)(sm + SM_W1 + (size_t)(sl * 16 + jg) * 256 + lane * 8);
                    #pragma unroll
                    for (int m2 = 0; m2 < 2; m2++)
                        mma_f16(C1[m2][j8], (const uint32_t*)&A[m2], B.x, B.y);
                }
            }
        }

        // ---- store prefetched chunk + indices ----
        if (valid) {
            #pragma unroll
            for (int ii = 0; ii < 8; ii++) {
                int idx = tid + ii * THREADS;
                float4 v = ev[ii];
                int e = idx >> 4, jf = idx & 15;
                int sl = jf >> 2;
                int rg = ((e >> 3) & 1) | (((jf >> 1) & 1) << 1);
                char* pbase = sm + SM_PING + (pb ^ 1) * 16384 +
                              (((e >> 4 << 2) + sl) << 9) + rg * 4;
                int j0 = 2 * jf;
                *(uint32_t*)(pbase + (((e & 7) << 2) | (j0 & 3)) * 16)       = pack_h2(v.x, v.y);
                *(uint32_t*)(pbase + (((e & 7) << 2) | ((j0 + 1) & 3)) * 16) = pack_h2(v.z, v.w);
            }
            if (tid < TILE) {
                ((int*)(sm + SM_RS))[(pb ^ 1) * TILE + tid] = nr;
                ((int*)(sm + SM_SS))[(pb ^ 1) * TILE + tid] = nss;
                atomicAdd(&g_cnts[nr], 1.0f);
            }
        }

        // ============ epilogue1: h = relu(C1 + P_r + P_s) -> fp16 frags =====
        #pragma unroll
        for (int m2 = 0; m2 < 2; m2++) {
            int mt = (wm << 1) + m2;
            int r0 = (mt << 4) + g;
            const int ra = rs[r0], rb = rs[r0 + 8];
            const int sa = ssn[r0], sb = ssn[r0 + 8];
            const int toff = t * 16 + wn * 8;
            #pragma unroll
            for (int jj = 0; jj < 2; jj++) {
                uint4 Ra = *(const uint4*)&g_Ph[(size_t)ra * 128 + toff + jj * 4];
                uint4 Rb = *(const uint4*)&g_Ph[(size_t)rb * 128 + toff + jj * 4];
                uint4 Sa = *(const uint4*)&g_Ph[(size_t)sa * 128 + 64 + toff + jj * 4];
                uint4 Sb = *(const uint4*)&g_Ph[(size_t)sb * 128 + 64 + toff + jj * 4];
                const uint32_t* pra = (const uint32_t*)&Ra;
                const uint32_t* prb = (const uint32_t*)&Rb;
                const uint32_t* psa = (const uint32_t*)&Sa;
                const uint32_t* psb = (const uint32_t*)&Sb;
                #pragma unroll
                for (int u2 = 0; u2 < 4; u2 += 2) {
                    uint4 H;
                    uint32_t* hp = (uint32_t*)&H;
                    #pragma unroll
                    for (int q = 0; q < 2; q++) {
                        int u = u2 + q;
                        int j8 = jj * 4 + u;
                        float2 fra = h2f2(pra[u]), frb = h2f2(prb[u]);
                        float2 fsa = h2f2(psa[u]), fsb = h2f2(psb[u]);
                        float v0 = fmaxf(C1[m2][j8][0] + fra.x + fsa.x, 0.f);
                        float v1 = fmaxf(C1[m2][j8][1] + fra.y + fsa.y, 0.f);
                        float v2 = fmaxf(C1[m2][j8][2] + frb.x + fsb.x, 0.f);
                        float v3 = fmaxf(C1[m2][j8][3] + frb.y + fsb.y, 0.f);
                        hp[q * 2 + 0] = pack_h2(v0, v1);
                        hp[q * 2 + 1] = pack_h2(v2, v3);
                    }
                    int sl2 = ((wn << 3) + jj * 4 + u2) >> 1;
                    *(uint4*)(sm + SM_AB + (((mt << 3) + sl2) << 9) + lane * 16) = H;
                }
            }
        }
        __syncthreads();   // S1: h frags + prefetch stores visible

        // ============ GEMM2 (reg-B): h[128,128] @ W_out =====================
        float C2[2][4][4];
        #pragma unroll
        for (int a = 0; a < 2; a++)
            #pragma unroll
            for (int b = 0; b < 4; b++)
                #pragma unroll
                for (int c = 0; c < 4; c++) C2[a][b][c] = 0.f;
        #pragma unroll
        for (int s2 = 0; s2 < 8; s2++) {
            uint4 A[2];
            #pragma unroll
            for (int m2 = 0; m2 < 2; m2++) {
                int mt = (wm << 1) + m2;
                A[m2] = *(const uint4*)(sm + SM_AB + (((mt << 3) + s2) << 9) + lane * 16);
            }
            #pragma unroll
            for (int j4 = 0; j4 < 4; j4++) {
                #pragma unroll
                for (int m2 = 0; m2 < 2; m2++)
                    mma_f16(C2[m2][j4], (const uint32_t*)&A[m2],
                            B2r[s2][j4].x, B2r[s2][j4].y);
            }
        }
        __syncthreads();   // S2: GEMM2 reads of AB done

        // ============ epilogue2: e_new -> v2 atomics + fp16 e frags =========
        #pragma unroll
        for (int m2 = 0; m2 < 2; m2++) {
            int mt = (wm << 1) + m2;
            int r0 = (mt << 4) + g;
            int n0 = rs[r0], n1 = rs[r0 + 8];
            #pragma unroll
            for (int j4e = 0; j4e < 4; j4e += 2) {
                uint4 E;
                uint32_t* ep = (uint32_t*)&E;
                #pragma unroll
                for (int q = 0; q < 2; q++) {
                    int j4 = j4e + q;
                    int col = (((wn << 2) + j4) << 3) + (t << 1);
                    float v0 = fmaxf(C2[m2][j4][0] + bo[col],     0.f);
                    float v1 = fmaxf(C2[m2][j4][1] + bo[col + 1], 0.f);
                    float v2 = fmaxf(C2[m2][j4][2] + bo[col],     0.f);
                    float v3 = fmaxf(C2[m2][j4][3] + bo[col + 1], 0.f);
                    atomicAdd((float2*)&g_sums[(size_t)n0 * DN + col], make_float2(v0, v1));
                    atomicAdd((float2*)&g_sums[(size_t)n1 * DN + col], make_float2(v2, v3));
                    ep[q * 2 + 0] = pack_h2(v0, v1);
                    ep[q * 2 + 1] = pack_h2(v2, v3);
                }
                int s3 = ((wn << 2) + j4e) >> 1;
                *(uint4*)(sm + SM_AB + (((mt << 2) + s3) << 9) + lane * 16) = E;
            }
        }
        __syncthreads();   // S3: e frags visible

        // ============ GEMM3 (reg-B): e[128,64] @ W_edge =====================
        float C3[2][4][4];
        #pragma unroll
        for (int a = 0; a < 2; a++)
            #pragma unroll
            for (int b = 0; b < 4; b++)
                #pragma unroll
                for (int c = 0; c < 4; c++) C3[a][b][c] = 0.f;
        #pragma unroll
        for (int s3 = 0; s3 < 4; s3++) {
            uint4 A[2];
            #pragma unroll
            for (int m2 = 0; m2 < 2; m2++) {
                int mt = (wm << 1) + m2;
                A[m2] = *(const uint4*)(sm + SM_AB + (((mt << 2) + s3) << 9) + lane * 16);
            }
            #pragma unroll
            for (int j4 = 0; j4 < 4; j4++) {
                #pragma unroll
                for (int m2 = 0; m2 < 2; m2++)
                    mma_f16(C3[m2][j4], (const uint32_t*)&A[m2],
                            B3r[s3][j4].x, B3r[s3][j4].y);
            }
        }
        __syncthreads();   // S4: GEMM3 reads done before next tile's AB writes

        // ============ epilogue3: edges_out ==================================
        #pragma unroll
        for (int m2 = 0; m2 < 2; m2++) {
            int row = e0 + (((wm << 1) + m2) << 4) + g;
            #pragma unroll
            for (int j4 = 0; j4 < 4; j4++) {
                int col = (((wn << 2) + j4) << 3) + (t << 1);
                float2 va, vb;
                va.x = fmaxf(C3[m2][j4][0] + be[col],     0.f);
                va.y = fmaxf(C3[m2][j4][1] + be[col + 1], 0.f);
                vb.x = fmaxf(C3[m2][j4][2] + be[col],     0.f);
                vb.y = fmaxf(C3[m2][j4][3] + be[col + 1], 0.f);
                *(float2*)(out_edges + (size_t)row       * DE + col) = va;
                *(float2*)(out_edges + (size_t)(row + 8) * DE + col) = vb;
            }
        }
    }
}

// ---------------------------------------------------------------------------
__global__ void finalize_kernel(float* __restrict__ out_nodes) {
    int base = blockIdx.x * blockDim.x * 4 + threadIdx.x;
    #pragma unroll
    for (int u = 0; u < 4; u++) {
        int i = base + u * blockDim.x;
        if (i < BN * (DN / 4)) {
            float c = g_cnts[i >> 4];
            float inv = (c > 0.f) ? (1.0f / c) : 0.f;
            float4 s = ((const float4*)g_sums)[i];
            s.x *= inv; s.y *= inv; s.z *= inv; s.w *= inv;
            ((float4*)out_nodes)[i] = s;
        }
    }
}

// ---------------------------------------------------------------------------
extern "C" void kernel_launch(void* const* d_in, const int* in_sizes, int n_in,
                              void* d_out, int out_size) {
    const float* nodes     = (const float*)d_in[0];
    const float* edges     = (const float*)d_in[1];
    const int*   senders   = (const int*)  d_in[2];
    const int*   receivers = (const int*)  d_in[3];
    const float* W_in      = (const float*)d_in[4];
    const float* b_in      = (const float*)d_in[5];
    const float* W_out     = (const float*)d_in[6];
    const float* b_out     = (const float*)d_in[7];
    const float* W_edge    = (const float*)d_in[8];
    const float* b_edge    = (const float*)d_in[9];

    float* out       = (float*)d_out;
    float* out_nodes = out;
    float* out_edges = out_nodes + (size_t)BN * DN;
    float* out_s     = out_edges + (size_t)BE * DE;
    float* out_r     = out_s + BE;

    cudaFuncSetAttribute(pnode_kernel,
                         cudaFuncAttributeMaxDynamicSharedMemorySize, PSM_TOTAL);
    cudaFuncSetAttribute(edge_kernel,
                         cudaFuncAttributeMaxDynamicSharedMemorySize, SMEM_TOTAL);

    int sm_count = 148;
    cudaDeviceGetAttribute(&sm_count, cudaDevAttrMultiProcessorCount, 0);

    // zero scratch via graph-legal async memsets (no allocation)
    void* p_sums = nullptr;
    void* p_cnts = nullptr;
    cudaGetSymbolAddress(&p_sums, g_sums);
    cudaGetSymbolAddress(&p_cnts, g_cnts);
    cudaMemsetAsync(p_sums, 0, (size_t)BN * DN * sizeof(float));
    cudaMemsetAsync(p_cnts, 0, (size_t)BN * sizeof(float));

    pnode_kernel<<<BN / PROWS, PTHREADS, PSM_TOTAL>>>(nodes, W_in, b_in);
    edge_kernel<<<sm_count, THREADS, SMEM_TOTAL>>>(
        edges, senders, receivers,
        W_in, W_out, b_out, W_edge, b_edge, out_edges, out_s, out_r);
    finalize_kernel<<<(BN * DN / 4 + 1023) / 1024, 256>>>(out_nodes);
}

// round 15
// speedup vs baseline: 1.0493x; 1.0493x over previous
#include <cuda_runtime.h>
#include <cuda_bf16.h>
#include <cuda_fp16.h>
#include <cstdint>

// Problem constants
#define NNODES 8192
#define DN  64
#define DE  64
#define IUU 128
#define BE  524288
#define BN  65536
#define TILE 128
#define NTILES (BE / TILE)     // 4096
#define THREADS 256            // 1 CTA per SM, high-register

// Device-global scratch (no allocation allowed)
__device__ float    g_sums[(size_t)BN * DN];   // 16 MB
__device__ float    g_cnts[BN];
// fp16 P table, thread-swizzled: per node 128 uint32 = [Pr 64 | Ps 64] packs.
__device__ uint32_t g_Ph[(size_t)BN * 128];    // 32 MB

// ---------------- edge-kernel smem layout (bytes) -- R12 layout ----------
#define SM_RS   0                        // 2 x 128 ints (double buffered)
#define SM_SS   1024                     // 2 x 128 ints
#define SM_BO   2048                     // 64 f
#define SM_BE2  2304                     // 64 f
#define SM_W1   4096                     // W_in edge part: 64 frags * 256 = 16384
#define SM_W2   20480                    // W_out staging: 16384
#define SM_W3   36864                    // W_edge staging: 8192
#define SM_AB   45056                    // h frags 32768 (fp16); e frags overlay first 16384
#define SM_PING 77824                    // 2 x 16384 edge-chunk fp16 frag buffers
#define SMEM_TOTAL 110592

// ---------------- pnode-kernel smem layout (persistent, 2 A-buffers) ------
#define PSM_W   0                        // 128 frags * 256B = 32768
#define PSM_A   32768                    // 2 x 16384 (128x64 fp16 A-frags each)
#define PSM_B   65536                    // 128 f bias
#define PSM_TOTAL 66048
#define PTHREADS 256
#define PBLOCKS  (BN / 128)              // 512

// ---------------------------------------------------------------------------
__device__ __forceinline__ void mma_f16(float* c, const uint32_t* a,
                                        uint32_t b0, uint32_t b1) {
    asm volatile(
        "mma.sync.aligned.m16n8k16.row.col.f32.f16.f16.f32 "
        "{%0,%1,%2,%3},{%4,%5,%6,%7},{%8,%9},{%0,%1,%2,%3};"
        : "+f"(c[0]), "+f"(c[1]), "+f"(c[2]), "+f"(c[3])
        : "r"(a[0]), "r"(a[1]), "r"(a[2]), "r"(a[3]), "r"(b0), "r"(b1));
}

__device__ __forceinline__ uint32_t pack_h2(float x, float y) {
    __half2 h = __floats2half2_rn(x, y);
    return *reinterpret_cast<uint32_t*>(&h);
}
__device__ __forceinline__ float2 h2f2(uint32_t w) {
    return __half22float2(*reinterpret_cast<__half2*>(&w));
}

// Weights -> fp16 B-frags, hi only (uint2/lane, 256B/frag). W [K, NT*8] row-major.
__device__ __forceinline__ void load_wfrag_h(const float* __restrict__ W, int K, int NT,
                                             char* dst, int wid, int lane, int nwarps) {
    const int g = lane >> 2, t = lane & 3;
    const int Nw = NT * 8;
    const int SF = K / 16;
    for (int f = wid; f < SF * NT; f += nwarps) {
        int s = f / NT, j = f - s * NT;
        int n = j * 8 + g;
        uint2 v;
        #pragma unroll
        for (int r = 0; r < 2; r++) {
            int k = s * 16 + 2 * t + 8 * r;
            ((uint32_t*)&v)[r] = pack_h2(W[(size_t)k * Nw + n], W[(size_t)(k + 1) * Nw + n]);
        }
        *(uint2*)(dst + (size_t)f * 256 + lane * 8) = v;
    }
}

// ---------------------------------------------------------------------------
// Persistent pnode: 296 CTAs, each handles node blocks bid and bid+gridDim.
// Ph[n] = fp16([nodes[n]@W_in[0:64]+b_in || nodes[n]@W_in[128:192]]), swizzled.
__global__ __launch_bounds__(PTHREADS, 2)
void pnode_kernel(const float* __restrict__ nodes,
                  const float* __restrict__ W_in,
                  const float* __restrict__ b_in)
{
    extern __shared__ char sm[];
    const int tid  = threadIdx.x;
    const int lane = tid & 31;
    const int wid  = tid >> 5;
    const int g = lane >> 2, t = lane & 3;
    const int wm = wid & 3;
    const int wn = wid >> 2;

    // ---- stage weights ONCE per CTA ----
    for (int f = wid; f < 4 * 32; f += (PTHREADS / 32)) {
        int s = f >> 5, j = f & 31;
        int n = j * 8 + g;
        uint2 v;
        #pragma unroll
        for (int r = 0; r < 2; r++) {
            int k = s * 16 + 2 * t + 8 * r;
            float x, y;
            if (n < 128) { x = W_in[(size_t)k * IUU + n];         y = W_in[(size_t)(k + 1) * IUU + n]; }
            else         { x = W_in[(size_t)(128 + k) * IUU + n - 128];
                           y = W_in[(size_t)(129 + k) * IUU + n - 128]; }
            ((uint32_t*)&v)[r] = pack_h2(x, y);
        }
        *(uint2*)(sm + PSM_W + (size_t)f * 256 + lane * 8) = v;
    }
    if (tid < IUU) ((float*)(sm + PSM_B))[tid] = b_in[tid];

    // ---- gather A for BOTH blocks up front (block 2 hidden under block 1) --
    const int blk0 = blockIdx.x;
    const int blk1 = blockIdx.x + gridDim.x;
    #pragma unroll
    for (int bb = 0; bb < 2; bb++) {
        int blk = bb ? blk1 : blk0;
        if (blk >= PBLOCKS) break;
        const float4* nbase = (const float4*)(nodes + (size_t)blk * 128 * DN);
        char* abuf = sm + PSM_A + bb * 16384;
        #pragma unroll
        for (int ii = 0; ii < 8; ii++) {
            int idx = tid + ii * PTHREADS;           // 2048 float4 units
            float4 v = nbase[idx];
            int e = idx >> 4, jf = idx & 15;
            int sl = jf >> 2;
            int rg = ((e >> 3) & 1) | (((jf >> 1) & 1) << 1);
            char* pbase = abuf + (((e >> 4 << 2) + sl) << 9) + rg * 4;
            int j0 = 2 * jf;
            *(uint32_t*)(pbase + (((e & 7) << 2) | (j0 & 3)) * 16)       = pack_h2(v.x, v.y);
            *(uint32_t*)(pbase + (((e & 7) << 2) | ((j0 + 1) & 3)) * 16) = pack_h2(v.z, v.w);
        }
    }
    __syncthreads();

    const float* bi = (const float*)(sm + PSM_B);
    #pragma unroll
    for (int bb = 0; bb < 2; bb++) {
        int blk = bb ? blk1 : blk0;
        if (blk >= PBLOCKS) break;
        const int m0 = blk * 128;
        const char* abuf = sm + PSM_A + bb * 16384;
        #pragma unroll
        for (int np = 0; np < 2; np++) {
            float C[2][8][4];
            #pragma unroll
            for (int a = 0; a < 2; a++)
                #pragma unroll
                for (int b = 0; b < 8; b++)
                    #pragma unroll
                    for (int c = 0; c < 4; c++) C[a][b][c] = 0.f;
            #pragma unroll
            for (int sl = 0; sl < 4; sl++) {
                uint4 A[2];
                #pragma unroll
                for (int m2 = 0; m2 < 2; m2++) {
                    int mt = (wm << 1) + m2;
                    A[m2] = *(const uint4*)(abuf + (((mt << 2) + sl) << 9) + lane * 16);
                }
                #pragma unroll
                for (int j8 = 0; j8 < 8; j8++) {
                    int jg = wn * 16 + np * 8 + j8;
                    uint2 B = *(const uint2*)(sm + PSM_W + (size_t)(sl * 32 + jg) * 256 + lane * 8);
                    #pragma unroll
                    for (int m2 = 0; m2 < 2; m2++)
                        mma_f16(C[m2][j8], (const uint32_t*)&A[m2], B.x, B.y);
                }
            }
            // vectorized store: 8 consecutive packs per (row, np)
            #pragma unroll
            for (int m2 = 0; m2 < 2; m2++) {
                int row = m0 + wm * 32 + m2 * 16 + g;
                uint32_t pa[8], pb[8];
                #pragma unroll
                for (int j8 = 0; j8 < 8; j8++) {
                    int col = (wn * 16 + np * 8 + j8) * 8 + t * 2;
                    float bx = (wn == 0) ? bi[col]     : 0.f;
                    float by = (wn == 0) ? bi[col + 1] : 0.f;
                    pa[j8] = pack_h2(C[m2][j8][0] + bx, C[m2][j8][1] + by);
                    pb[j8] = pack_h2(C[m2][j8][2] + bx, C[m2][j8][3] + by);
                }
                size_t base = (size_t)row * 128 + wn * 64 + t * 16 + np * 8;
                *(uint4*)&g_Ph[base]     = *(uint4*)&pa[0];
                *(uint4*)&g_Ph[base + 4] = *(uint4*)&pa[4];
                size_t base2 = base + (size_t)8 * 128;
                *(uint4*)&g_Ph[base2]     = *(uint4*)&pb[0];
                *(uint4*)&g_Ph[base2 + 4] = *(uint4*)&pb[4];
            }
        }
    }
}

// ---------------------------------------------------------------------------
// 256 threads, 1 CTA/SM, persistent-register B (R12 structure, 4 barriers).
__global__ __launch_bounds__(THREADS, 1)
void edge_kernel(const float* __restrict__ edges,
                 const int*   __restrict__ senders,
                 const int*   __restrict__ receivers,
                 const float* __restrict__ W_in,
                 const float* __restrict__ W_out, const float* __restrict__ b_out,
                 const float* __restrict__ W_edge,const float* __restrict__ b_edge,
                 float* __restrict__ out_edges,
                 float* __restrict__ out_s, float* __restrict__ out_r)
{
    extern __shared__ char sm[];
    const int tid  = threadIdx.x;
    const int lane = tid & 31;
    const int wid  = tid >> 5;
    const int g = lane >> 2, t = lane & 3;
    const int wm = wid & 3;                 // M band: rows 32*wm (2 frags)
    const int wn = wid >> 2;                // N half (0/1)

    load_wfrag_h(W_in + 64 * IUU, 64, 16, sm + SM_W1, wid, lane, THREADS / 32);
    load_wfrag_h(W_out, 128, 8, sm + SM_W2, wid, lane, THREADS / 32);
    load_wfrag_h(W_edge, 64, 8, sm + SM_W3, wid, lane, THREADS / 32);
    if (tid < DN) ((float*)(sm + SM_BO))[tid]  = b_out[tid];
    if (tid < DE) ((float*)(sm + SM_BE2))[tid] = b_edge[tid];
    __syncthreads();

    // persistent-register B fragments for GEMM2 / GEMM3
    uint2 B2r[8][4];
    #pragma unroll
    for (int s2 = 0; s2 < 8; s2++)
        #pragma unroll
        for (int j4 = 0; j4 < 4; j4++)
            B2r[s2][j4] = *(const uint2*)(sm + SM_W2 +
                          (size_t)(s2 * 8 + (wn << 2) + j4) * 256 + lane * 8);
    uint2 B3r[4][4];
    #pragma unroll
    for (int s3 = 0; s3 < 4; s3++)
        #pragma unroll
        for (int j4 = 0; j4 < 4; j4++)
            B3r[s3][j4] = *(const uint2*)(sm + SM_W3 +
                          (size_t)(s3 * 8 + (wn << 2) + j4) * 256 + lane * 8);

    const float* bo = (const float*)(sm + SM_BO);
    const float* be = (const float*)(sm + SM_BE2);

    // prologue: tile0 indices + edge chunk (fp16) into buffer 0
    {
        int tile0 = blockIdx.x;
        if (tid < TILE) {
            int ge = tile0 * TILE + tid, b = ge >> 16;
            int rraw = receivers[ge], sraw = senders[ge];
            out_r[ge] = (float)rraw;
            out_s[ge] = (float)sraw;
            int nr = rraw + (b << 13);
            ((int*)(sm + SM_RS))[tid] = nr;
            ((int*)(sm + SM_SS))[tid] = sraw + (b << 13);
            atomicAdd(&g_cnts[nr], 1.0f);
        }
        const float4* ebase = (const float4*)(edges + (size_t)tile0 * TILE * DE);
        #pragma unroll
        for (int ii = 0; ii < 8; ii++) {
            int idx = tid + ii * THREADS;
            float4 v = ebase[idx];
            int e = idx >> 4, jf = idx & 15;
            int sl = jf >> 2;
            int rg = ((e >> 3) & 1) | (((jf >> 1) & 1) << 1);
            char* pbase = sm + SM_PING + (((e >> 4 << 2) + sl) << 9) + rg * 4;
            int j0 = 2 * jf;
            *(uint32_t*)(pbase + (((e & 7) << 2) | (j0 & 3)) * 16)       = pack_h2(v.x, v.y);
            *(uint32_t*)(pbase + (((e & 7) << 2) | ((j0 + 1) & 3)) * 16) = pack_h2(v.z, v.w);
        }
    }
    __syncthreads();

    int pb = 0;
    for (int tile = blockIdx.x; tile < NTILES; tile += gridDim.x, pb ^= 1) {
        const int e0 = tile * TILE;
        const int* rs  = (const int*)(sm + SM_RS) + pb * TILE;
        const int* ssn = (const int*)(sm + SM_SS) + pb * TILE;

        // ---- prefetch next tile ----
        const int nt = tile + (int)gridDim.x;
        const bool valid = nt < NTILES;
        float4 ev[8];
        int nr = 0, nss = 0;
        if (valid) {
            const float4* ebase = (const float4*)(edges + (size_t)nt * TILE * DE);
            #pragma unroll
            for (int ii = 0; ii < 8; ii++) ev[ii] = ebase[tid + ii * THREADS];
            if (tid < TILE) {
                int ge = nt * TILE + tid, b = ge >> 16;
                int rraw = receivers[ge], sraw = senders[ge];
                out_r[ge] = (float)rraw;
                out_s[ge] = (float)sraw;
                nr  = rraw + (b << 13);
                nss = sraw + (b << 13);
            }
        }

        // ============ GEMM1 (edge chunk, 1-term): [128,64] @ W1h ============
        float C1[2][8][4];
        #pragma unroll
        for (int a = 0; a < 2; a++)
            #pragma unroll
            for (int b = 0; b < 8; b++)
                #pragma unroll
                for (int c = 0; c < 4; c++) C1[a][b][c] = 0.f;
        {
            const char* abase = sm + SM_PING + pb * 16384;
            #pragma unroll
            for (int sl = 0; sl < 4; sl++) {
                uint4 A[2];
                #pragma unroll
                for (int m2 = 0; m2 < 2; m2++) {
                    int mt = (wm << 1) + m2;
                    A[m2] = *(const uint4*)(abase + (((mt << 2) + sl) << 9) + lane * 16);
                }
                #pragma unroll
                for (int j8 = 0; j8 < 8; j8++) {
                    int jg = (wn << 3) + j8;
                    uint2 B = *(const uint2*)(sm + SM_W1 + (size_t)(sl * 16 + jg) * 256 + lane * 8);
                    #pragma unroll
                    for (int m2 = 0; m2 < 2; m2++)
                        mma_f16(C1[m2][j8], (const uint32_t*)&A[m2], B.x, B.y);
                }
            }
        }

        // ---- store prefetched chunk + indices ----
        if (valid) {
            #pragma unroll
            for (int ii = 0; ii < 8; ii++) {
                int idx = tid + ii * THREADS;
                float4 v = ev[ii];
                int e = idx >> 4, jf = idx & 15;
                int sl = jf >> 2;
                int rg = ((e >> 3) & 1) | (((jf >> 1) & 1) << 1);
                char* pbase = sm + SM_PING + (pb ^ 1) * 16384 +
                              (((e >> 4 << 2) + sl) << 9) + rg * 4;
                int j0 = 2 * jf;
                *(uint32_t*)(pbase + (((e & 7) << 2) | (j0 & 3)) * 16)       = pack_h2(v.x, v.y);
                *(uint32_t*)(pbase + (((e & 7) << 2) | ((j0 + 1) & 3)) * 16) = pack_h2(v.z, v.w);
            }
            if (tid < TILE) {
                ((int*)(sm + SM_RS))[(pb ^ 1) * TILE + tid] = nr;
                ((int*)(sm + SM_SS))[(pb ^ 1) * TILE + tid] = nss;
                atomicAdd(&g_cnts[nr], 1.0f);
            }
        }

        // ============ epilogue1: h = relu(C1 + P_r + P_s) -> fp16 frags =====
        #pragma unroll
        for (int m2 = 0; m2 < 2; m2++) {
            int mt = (wm << 1) + m2;
            int r0 = (mt << 4) + g;
            const int ra = rs[r0], rb = rs[r0 + 8];
            const int sa = ssn[r0], sb = ssn[r0 + 8];
            const int toff = t * 16 + wn * 8;
            #pragma unroll
            for (int jj = 0; jj < 2; jj++) {
                uint4 Ra = *(const uint4*)&g_Ph[(size_t)ra * 128 + toff + jj * 4];
                uint4 Rb = *(const uint4*)&g_Ph[(size_t)rb * 128 + toff + jj * 4];
                uint4 Sa = *(const uint4*)&g_Ph[(size_t)sa * 128 + 64 + toff + jj * 4];
                uint4 Sb = *(const uint4*)&g_Ph[(size_t)sb * 128 + 64 + toff + jj * 4];
                const uint32_t* pra = (const uint32_t*)&Ra;
                const uint32_t* prb = (const uint32_t*)&Rb;
                const uint32_t* psa = (const uint32_t*)&Sa;
                const uint32_t* psb = (const uint32_t*)&Sb;
                #pragma unroll
                for (int u2 = 0; u2 < 4; u2 += 2) {
                    uint4 H;
                    uint32_t* hp = (uint32_t*)&H;
                    #pragma unroll
                    for (int q = 0; q < 2; q++) {
                        int u = u2 + q;
                        int j8 = jj * 4 + u;
                        float2 fra = h2f2(pra[u]), frb = h2f2(prb[u]);
                        float2 fsa = h2f2(psa[u]), fsb = h2f2(psb[u]);
                        float v0 = fmaxf(C1[m2][j8][0] + fra.x + fsa.x, 0.f);
                        float v1 = fmaxf(C1[m2][j8][1] + fra.y + fsa.y, 0.f);
                        float v2 = fmaxf(C1[m2][j8][2] + frb.x + fsb.x, 0.f);
                        float v3 = fmaxf(C1[m2][j8][3] + frb.y + fsb.y, 0.f);
                        hp[q * 2 + 0] = pack_h2(v0, v1);
                        hp[q * 2 + 1] = pack_h2(v2, v3);
                    }
                    int sl2 = ((wn << 3) + jj * 4 + u2) >> 1;
                    *(uint4*)(sm + SM_AB + (((mt << 3) + sl2) << 9) + lane * 16) = H;
                }
            }
        }
        __syncthreads();   // S1: h frags + prefetch stores visible

        // ============ GEMM2 (reg-B): h[128,128] @ W_out =====================
        float C2[2][4][4];
        #pragma unroll
        for (int a = 0; a < 2; a++)
            #pragma unroll
            for (int b = 0; b < 4; b++)
                #pragma unroll
                for (int c = 0; c < 4; c++) C2[a][b][c] = 0.f;
        #pragma unroll
        for (int s2 = 0; s2 < 8; s2++) {
            uint4 A[2];
            #pragma unroll
            for (int m2 = 0; m2 < 2; m2++) {
                int mt = (wm << 1) + m2;
                A[m2] = *(const uint4*)(sm + SM_AB + (((mt << 3) + s2) << 9) + lane * 16);
            }
            #pragma unroll
            for (int j4 = 0; j4 < 4; j4++) {
                #pragma unroll
                for (int m2 = 0; m2 < 2; m2++)
                    mma_f16(C2[m2][j4], (const uint32_t*)&A[m2],
                            B2r[s2][j4].x, B2r[s2][j4].y);
            }
        }
        __syncthreads();   // S2: GEMM2 reads of AB done

        // ============ epilogue2: e_new -> v2 atomics + fp16 e frags =========
        #pragma unroll
        for (int m2 = 0; m2 < 2; m2++) {
            int mt = (wm << 1) + m2;
            int r0 = (mt << 4) + g;
            int n0 = rs[r0], n1 = rs[r0 + 8];
            #pragma unroll
            for (int j4e = 0; j4e < 4; j4e += 2) {
                uint4 E;
                uint32_t* ep = (uint32_t*)&E;
                #pragma unroll
                for (int q = 0; q < 2; q++) {
                    int j4 = j4e + q;
                    int col = (((wn << 2) + j4) << 3) + (t << 1);
                    float v0 = fmaxf(C2[m2][j4][0] + bo[col],     0.f);
                    float v1 = fmaxf(C2[m2][j4][1] + bo[col + 1], 0.f);
                    float v2 = fmaxf(C2[m2][j4][2] + bo[col],     0.f);
                    float v3 = fmaxf(C2[m2][j4][3] + bo[col + 1], 0.f);
                    atomicAdd((float2*)&g_sums[(size_t)n0 * DN + col], make_float2(v0, v1));
                    atomicAdd((float2*)&g_sums[(size_t)n1 * DN + col], make_float2(v2, v3));
                    ep[q * 2 + 0] = pack_h2(v0, v1);
                    ep[q * 2 + 1] = pack_h2(v2, v3);
                }
                int s3 = ((wn << 2) + j4e) >> 1;
                *(uint4*)(sm + SM_AB + (((mt << 2) + s3) << 9) + lane * 16) = E;
            }
        }
        __syncthreads();   // S3: e frags visible

        // ============ GEMM3 (reg-B): e[128,64] @ W_edge =====================
        float C3[2][4][4];
        #pragma unroll
        for (int a = 0; a < 2; a++)
            #pragma unroll
            for (int b = 0; b < 4; b++)
                #pragma unroll
                for (int c = 0; c < 4; c++) C3[a][b][c] = 0.f;
        #pragma unroll
        for (int s3 = 0; s3 < 4; s3++) {
            uint4 A[2];
            #pragma unroll
            for (int m2 = 0; m2 < 2; m2++) {
                int mt = (wm << 1) + m2;
                A[m2] = *(const uint4*)(sm + SM_AB + (((mt << 2) + s3) << 9) + lane * 16);
            }
            #pragma unroll
            for (int j4 = 0; j4 < 4; j4++) {
                #pragma unroll
                for (int m2 = 0; m2 < 2; m2++)
                    mma_f16(C3[m2][j4], (const uint32_t*)&A[m2],
                            B3r[s3][j4].x, B3r[s3][j4].y);
            }
        }
        __syncthreads();   // S4: GEMM3 reads done before next tile's AB writes

        // ============ epilogue3: edges_out ==================================
        #pragma unroll
        for (int m2 = 0; m2 < 2; m2++) {
            int row = e0 + (((wm << 1) + m2) << 4) + g;
            #pragma unroll
            for (int j4 = 0; j4 < 4; j4++) {
                int col = (((wn << 2) + j4) << 3) + (t << 1);
                float2 va, vb;
                va.x = fmaxf(C3[m2][j4][0] + be[col],     0.f);
                va.y = fmaxf(C3[m2][j4][1] + be[col + 1], 0.f);
                vb.x = fmaxf(C3[m2][j4][2] + be[col],     0.f);
                vb.y = fmaxf(C3[m2][j4][3] + be[col + 1], 0.f);
                *(float2*)(out_edges + (size_t)row       * DE + col) = va;
                *(float2*)(out_edges + (size_t)(row + 8) * DE + col) = vb;
            }
        }
    }
}

// ---------------------------------------------------------------------------
__global__ void finalize_kernel(float* __restrict__ out_nodes) {
    int base = blockIdx.x * blockDim.x * 4 + threadIdx.x;
    #pragma unroll
    for (int u = 0; u < 4; u++) {
        int i = base + u * blockDim.x;
        if (i < BN * (DN / 4)) {
            float c = g_cnts[i >> 4];
            float inv = (c > 0.f) ? (1.0f / c) : 0.f;
            float4 s = ((const float4*)g_sums)[i];
            s.x *= inv; s.y *= inv; s.z *= inv; s.w *= inv;
            ((float4*)out_nodes)[i] = s;
        }
    }
}

// ---------------------------------------------------------------------------
extern "C" void kernel_launch(void* const* d_in, const int* in_sizes, int n_in,
                              void* d_out, int out_size) {
    const float* nodes     = (const float*)d_in[0];
    const float* edges     = (const float*)d_in[1];
    const int*   senders   = (const int*)  d_in[2];
    const int*   receivers = (const int*)  d_in[3];
    const float* W_in      = (const float*)d_in[4];
    const float* b_in      = (const float*)d_in[5];
    const float* W_out     = (const float*)d_in[6];
    const float* b_out     = (const float*)d_in[7];
    const float* W_edge    = (const float*)d_in[8];
    const float* b_edge    = (const float*)d_in[9];

    float* out       = (float*)d_out;
    float* out_nodes = out;
    float* out_edges = out_nodes + (size_t)BN * DN;
    float* out_s     = out_edges + (size_t)BE * DE;
    float* out_r     = out_s + BE;

    cudaFuncSetAttribute(pnode_kernel,
                         cudaFuncAttributeMaxDynamicSharedMemorySize, PSM_TOTAL);
    cudaFuncSetAttribute(edge_kernel,
                         cudaFuncAttributeMaxDynamicSharedMemorySize, SMEM_TOTAL);

    int sm_count = 148;
    cudaDeviceGetAttribute(&sm_count, cudaDevAttrMultiProcessorCount, 0);

    // zero scratch via graph-legal async memsets (no allocation)
    void* p_sums = nullptr;
    void* p_cnts = nullptr;
    cudaGetSymbolAddress(&p_sums, g_sums);
    cudaGetSymbolAddress(&p_cnts, g_cnts);
    cudaMemsetAsync(p_sums, 0, (size_t)BN * DN * sizeof(float));
    cudaMemsetAsync(p_cnts, 0, (size_t)BN * sizeof(float));

    pnode_kernel<<<2 * sm_count, PTHREADS, PSM_TOTAL>>>(nodes, W_in, b_in);
    edge_kernel<<<sm_count, THREADS, SMEM_TOTAL>>>(
        edges, senders, receivers,
        W_in, W_out, b_out, W_edge, b_edge, out_edges, out_s, out_r);
    finalize_kernel<<<(BN * DN / 4 + 1023) / 1024, 256>>>(out_nodes);
}